// round 5
// baseline (speedup 1.0000x reference)
#include <cuda_runtime.h>

// YOLOLossv3 fused loss on GB300 (sm_103a).
// Inputs (metadata order): out[32,18,128,128] f32, gt_batch[1920] i32,
// gt_boxes[1920,4] f32, size_h i32[1], size_w i32[1]. Output: f32 scalar.

#define NB 32
#define NA 3
#define NH 128
#define NW 128
#define CH 18              // NA * (CLS+5)
#define PLANE (NH*NW)      // 16384 = 2^14
#define NCELL (NB*NA*NH*NW) // 1,572,864

// ---- device scratch (static; no allocation allowed) ----
__device__ unsigned char d_mask[NCELL];    // 1 => not-noobj (obj or ignored)
__device__ int           d_winner[NCELL];  // last (max-index) gt owning an obj cell
__device__ double        g_bbox, g_objbce, g_nobce;
__device__ unsigned int  g_nobj, g_nno, g_done;

__device__ __forceinline__ float anchW(int a) { return a == 0 ? 116.f : (a == 1 ? 156.f : 373.f); }
__device__ __forceinline__ float anchH(int a) { return a == 0 ?  90.f : (a == 1 ? 198.f : 326.f); }

struct GT {
    int   b, gi, gj, best;
    float gx, gy, gw, gh;
    float iou0, iou1, iou2;
};

__device__ __forceinline__ GT load_gt(const int* __restrict__ gtb,
                                      const float* __restrict__ gtx,
                                      int g, float strw, float strh) {
    GT r;
    float4 v = *reinterpret_cast<const float4*>(gtx + 4 * g);
    r.gx = v.x * (float)NW;
    r.gy = v.y * (float)NH;
    r.gw = v.z * (float)NW;
    r.gh = v.w * (float)NH;
    r.gi = (int)r.gx;   // gx > 0 => trunc == floor (matches astype(int32))
    r.gj = (int)r.gy;
    r.b  = gtb[g];
    float iou[3];
    float bi = -1.f; r.best = 0;
#pragma unroll
    for (int a = 0; a < 3; a++) {
        float aw = anchW(a) / strw, ah = anchH(a) / strh;
        float inter = fminf(r.gw, aw) * fminf(r.gh, ah);
        float uni   = r.gw * r.gh + aw * ah - inter;
        float io    = inter / uni;
        iou[a] = io;
        if (io > bi) { bi = io; r.best = a; }   // strict > : first max wins (argmax)
    }
    r.iou0 = iou[0]; r.iou1 = iou[1]; r.iou2 = iou[2];
    return r;
}

__device__ __forceinline__ int cell_of(int b, int a, int gj, int gi) {
    return ((b * NA + a) * NH + gj) * NW + gi;
}

__device__ __forceinline__ float sigm(float x)  { return 1.f / (1.f + expf(-x)); }
__device__ __forceinline__ float clipp(float p) { return fminf(fmaxf(p, 1e-7f), 0.99999988f); }

// ---- K1: clear mask, reset winner at gt cells, zero accumulators ----
__global__ void k_init(const int* __restrict__ gtb, const float* __restrict__ gtx,
                       int G, const int* __restrict__ psh, const int* __restrict__ psw) {
    int t = blockIdx.x * blockDim.x + threadIdx.x;
    if (t < NCELL / 16)
        reinterpret_cast<int4*>(d_mask)[t] = make_int4(0, 0, 0, 0);
    if (t < G) {
        float strw = (float)(psw[0] / NW);
        float strh = (float)(psh[0] / NH);
        GT r = load_gt(gtb, gtx, t, strw, strh);
        d_winner[cell_of(r.b, r.best, r.gj, r.gi)] = -1;   // idempotent, race-free
    }
    if (t == 0) {
        g_bbox = 0.0; g_objbce = 0.0; g_nobce = 0.0;
        g_nobj = 0u;  g_nno = 0u;     g_done = 0u;
    }
}

// ---- K2: scatter obj / ignore marks + last-gt-wins winner ----
__global__ void k_scatter(const int* __restrict__ gtb, const float* __restrict__ gtx,
                          int G, const int* __restrict__ psh, const int* __restrict__ psw) {
    int g = blockIdx.x * blockDim.x + threadIdx.x;
    if (g >= G) return;
    float strw = (float)(psw[0] / NW);
    float strh = (float)(psh[0] / NH);
    GT r = load_gt(gtb, gtx, g, strw, strh);
    float iou[3] = { r.iou0, r.iou1, r.iou2 };
    d_mask[cell_of(r.b, r.best, r.gj, r.gi)] = 1;               // obj cell
#pragma unroll
    for (int a = 0; a < 3; a++)
        if (iou[a] > 0.5f) d_mask[cell_of(r.b, a, r.gj, r.gi)] = 1;  // ignore region
    atomicMax(&d_winner[cell_of(r.b, r.best, r.gj, r.gi)], g);
}

// ---- K3: dense noobj BCE + per-winner-GT obj loss + last-block finalize ----
__global__ void k_main(const float* __restrict__ out,
                       const int* __restrict__ gtb, const float* __restrict__ gtx,
                       int G, const int* __restrict__ psh, const int* __restrict__ psw,
                       float* __restrict__ res) {
    int t = blockIdx.x * blockDim.x + threadIdx.x;

    // --- per-GT obj loss (threads [0, G)) ---
    if (t < G) {
        float strw = (float)(psw[0] / NW);
        float strh = (float)(psh[0] / NH);
        GT r = load_gt(gtb, gtx, t, strw, strh);
        int cell = cell_of(r.b, r.best, r.gj, r.gi);
        if (d_winner[cell] == t) {       // winner == sequential-scatter last-wins
            int base = ((r.b * CH + r.best * 6) * NH + r.gj) * NW + r.gi;
            float px = out[base];
            float py = out[base + 1 * PLANE];
            float pw = out[base + 2 * PLANE];
            float ph = out[base + 3 * PLANE];
            float pc = out[base + 4 * PLANE];

            float tx = r.gx - floorf(r.gx);
            float ty = r.gy - floorf(r.gy);
            float tw = logf(r.gw / (anchW(r.best) / strw));
            float th = logf(r.gh / (anchH(r.best) / strh));

            float sx = sigm(px), sy = sigm(py);
            float bbox = (sx - tx) * (sx - tx) + (sy - ty) * (sy - ty)
                       + (pw - tw) * (pw - tw) + (ph - th) * (ph - th);
            float p = clipp(sigm(pc));

            atomicAdd(&g_bbox,   (double)bbox);
            atomicAdd(&g_objbce, (double)(-logf(p)));
            atomicAdd(&g_nobj,   1u);
        }
    }

    // --- dense noobj BCE over the conf channel (4 cells/thread) ---
    float s = 0.f;
    int   c = 0;
    int n4 = t * 4;
    if (n4 < NCELL) {
        int seg = n4 >> 14;              // b*NA + a
        int b = seg / NA, a = seg - NA * b;
        const float4 x = *reinterpret_cast<const float4*>(
            out + ((b * CH + a * 6 + 4) << 14) + (n4 & (PLANE - 1)));
        uchar4 mk = *reinterpret_cast<const uchar4*>(d_mask + n4);
        float xv[4] = { x.x, x.y, x.z, x.w };
        unsigned char mv[4] = { mk.x, mk.y, mk.z, mk.w };
#pragma unroll
        for (int i = 0; i < 4; i++) {
            if (!mv[i]) {
                float p = clipp(sigm(xv[i]));
                s += -logf(1.f - p);
                c += 1;
            }
        }
    }
#pragma unroll
    for (int o = 16; o > 0; o >>= 1) {
        s += __shfl_down_sync(0xffffffffu, s, o);
        c += __shfl_down_sync(0xffffffffu, c, o);
    }
    __shared__ float ws[8];
    __shared__ int   wc[8];
    int lane = threadIdx.x & 31, w = threadIdx.x >> 5;
    if (lane == 0) { ws[w] = s; wc[w] = c; }
    __syncthreads();

    __shared__ bool amLast;
    if (threadIdx.x == 0) {
        float S = 0.f; int C = 0;
        int nw = blockDim.x >> 5;
        for (int i = 0; i < nw; i++) { S += ws[i]; C += wc[i]; }
        atomicAdd(&g_nobce, (double)S);
        atomicAdd(&g_nno, (unsigned int)C);
        __threadfence();
        unsigned int prev = atomicAdd(&g_done, 1u);
        amLast = (prev == gridDim.x - 1);
    }
    __syncthreads();

    // --- last block finalizes the scalar ---
    if (amLast && threadIdx.x == 0) {
        double nobj = g_nobj > 0u ? (double)g_nobj : 1.0;
        double nno  = g_nno  > 0u ? (double)g_nno  : 1.0;
        res[0] = (float)(g_bbox / nobj + g_objbce / nobj + 100.0 * g_nobce / nno);
    }
}

extern "C" void kernel_launch(void* const* d_in, const int* in_sizes, int n_in,
                              void* d_out, int out_size) {
    const float* out_t = (const float*)d_in[0];
    const int*   gtb   = (const int*)d_in[1];
    const float* gtx   = (const float*)d_in[2];
    const int*   psh   = (const int*)d_in[3];
    const int*   psw   = (const int*)d_in[4];
    float*       res   = (float*)d_out;
    int G = in_sizes[1];
    (void)n_in; (void)out_size;

    k_init   <<<(NCELL / 16 + 255) / 256, 256>>>(gtb, gtx, G, psh, psw);
    k_scatter<<<(G + 255) / 256, 256>>>(gtb, gtx, G, psh, psw);
    k_main   <<<(NCELL / 4 + 255) / 256, 256>>>(out_t, gtb, gtx, G, psh, psw, res);
}